// round 13
// baseline (speedup 1.0000x reference)
#include <cuda_runtime.h>

#define NR      96
#define DIM     768
#define TRIU    4560
#define P_CNT   9120
#define Q_CNT   9216
#define THR     0.3f
#define SPLITK  8              // 768/8 = 96 per split
#define KS      96
#define NEG_SL  16
#define NEG_PER 576
#define POS_GR  9
#define HTHR    1024
#define HB      (NEG_SL * POS_GR)   // 144 (proven counter geometry)

// ---------------- device scratch ----------------
__device__ float g_partPos[SPLITK * P_CNT];
__device__ float g_partNeg[SPLITK * Q_CNT];
__device__ float g_partDiag[SPLITK * 2 * NR];
__device__ int   g_pairIdx[P_CNT];      // (i<<8)|j, local 0..95
__device__ float g_sumP[POS_GR];
__device__ float g_sumN[NEG_SL];
__device__ float g_blockSum[HB];
__device__ unsigned g_count = 0;

__device__ __forceinline__ int triu_idx(int i, int j) {
    return i * (191 - i) / 2 + (j - i - 1);
}

// block reduce; sbuf has 32 slots; works for 128..1024 threads
__device__ __forceinline__ float blockReduce(float v, float* sbuf) {
    __syncthreads();
    int t = threadIdx.x;
    int nw = blockDim.x >> 5;
    #pragma unroll
    for (int o = 16; o; o >>= 1) v += __shfl_down_sync(0xffffffffu, v, o);
    if ((t & 31) == 0) sbuf[t >> 5] = v;
    __syncthreads();
    float r = 0.f;
    if (t < 32) {
        r = (t < nw) ? sbuf[t] : 0.f;
        #pragma unroll
        for (int o = 16; o; o >>= 1) r += __shfl_down_sync(0xffffffffu, r, o);
    }
    return r;   // valid at t == 0
}

// ---------------- K1: RAW grams + diag + pair index (168 blocks x 256) ----
__global__ void __launch_bounds__(256) k_gram(const float* __restrict__ S,
                                              const float* __restrict__ A) {
    __shared__ float As[KS][34];
    __shared__ float Bs[KS][34];

    int bx = blockIdx.x;
    int sk = bx / 21;
    int tl = bx % 21;

    int m, tr, tc;
    if (tl < 9) { m = 0; tr = tl / 3; tc = tl % 3; }
    else {
        int q = tl - 9;
        m = 1 + q / 6;
        const int TR6[6] = {0,0,0,1,1,2};
        const int TC6[6] = {0,1,2,1,2,2};
        tr = TR6[q % 6]; tc = TC6[q % 6];
    }
    // m0: neg = A x S^T; m1: S x S^T; m2: A x A^T
    const float* Ap = (m == 1) ? S : A;
    const float* Bp = (m == 2) ? A : S;

    int t  = threadIdx.x;
    int tx = t & 15, ty = t >> 4;
    int kb = sk * KS;

    // ---- prefetch whole 32x96 panels (3 float4 per thread per matrix) ----
    float4 ra[3], rb[3];
    #pragma unroll
    for (int p = 0; p < 3; p++) {
        int idx = t + p * 256;          // 0..767
        int row = idx / 24;             // 0..31
        int f4  = idx % 24;             // 0..23
        ra[p] = *(const float4*)&Ap[(tr * 32 + row) * DIM + kb + f4 * 4];
        rb[p] = *(const float4*)&Bp[(tc * 32 + row) * DIM + kb + f4 * 4];
    }
    #pragma unroll
    for (int p = 0; p < 3; p++) {
        int idx = t + p * 256;
        int row = idx / 24;
        int kk  = (idx % 24) * 4;
        As[kk + 0][row] = ra[p].x; As[kk + 1][row] = ra[p].y;
        As[kk + 2][row] = ra[p].z; As[kk + 3][row] = ra[p].w;
        Bs[kk + 0][row] = rb[p].x; Bs[kk + 1][row] = rb[p].y;
        Bs[kk + 2][row] = rb[p].z; Bs[kk + 3][row] = rb[p].w;
    }
    __syncthreads();

    float acc00 = 0.f, acc01 = 0.f, acc10 = 0.f, acc11 = 0.f;
    #pragma unroll 8
    for (int kk = 0; kk < KS; kk++) {
        float2 a = *(const float2*)&As[kk][2 * ty];
        float2 b = *(const float2*)&Bs[kk][2 * tx];
        acc00 += a.x * b.x; acc01 += a.x * b.y;
        acc10 += a.y * b.x; acc11 += a.y * b.y;
    }

    int r0 = tr * 32 + 2 * ty;
    int c0 = tc * 32 + 2 * tx;
    if (m == 0) {
        float* dst = g_partNeg + sk * Q_CNT;
        dst[r0 * 96 + c0]           = acc00;
        dst[r0 * 96 + c0 + 1]       = acc01;
        dst[(r0 + 1) * 96 + c0]     = acc10;
        dst[(r0 + 1) * 96 + c0 + 1] = acc11;
    } else {
        int base = (m == 2) ? TRIU : 0;
        float* dst = g_partPos + sk * P_CNT + base;
        if (r0     < c0    ) dst[triu_idx(r0,     c0    )] = acc00;
        if (r0     < c0 + 1) dst[triu_idx(r0,     c0 + 1)] = acc01;
        if (r0 + 1 < c0    ) dst[triu_idx(r0 + 1, c0    )] = acc10;
        if (r0 + 1 < c0 + 1) dst[triu_idx(r0 + 1, c0 + 1)] = acc11;
        if (r0 == c0) {  // diagonal entries -> squared row norms
            int off = (m == 1) ? 0 : NR;
            g_partDiag[sk * 2 * NR + off + r0]     = acc00;
            g_partDiag[sk * 2 * NR + off + r0 + 1] = acc11;
        }
        if (sk == 0) {   // pair index table (once per tile)
            int* pidx = g_pairIdx + base;
            if (r0     < c0    ) pidx[triu_idx(r0,     c0    )] = (r0 << 8)       | c0;
            if (r0     < c0 + 1) pidx[triu_idx(r0,     c0 + 1)] = (r0 << 8)       | (c0 + 1);
            if (r0 + 1 < c0    ) pidx[triu_idx(r0 + 1, c0    )] = ((r0 + 1) << 8) | c0;
            if (r0 + 1 < c0 + 1) pidx[triu_idx(r0 + 1, c0 + 1)] = ((r0 + 1) << 8) | (c0 + 1);
        }
    }
}

// ---------------- K2: combine + hinge + fused final (144 x 1024) ----------
__global__ void __launch_bounds__(HTHR, 1) k_hinge(float* __restrict__ out) {
    __shared__ __align__(16) float s_neg[NEG_PER];
    __shared__ float s_inv[2 * NR];
    __shared__ float sbuf[32];
    __shared__ bool s_last;

    int bid = blockIdx.x;
    int ns  = bid / POS_GR;       // 0..15
    int pg  = bid % POS_GR;       // 0..8
    int t   = threadIdx.x;

    // --- inverse norms (t < 192)
    if (t < 2 * NR) {
        float d = ((g_partDiag[0 * 192 + t] + g_partDiag[1 * 192 + t]) +
                   (g_partDiag[2 * 192 + t] + g_partDiag[3 * 192 + t])) +
                  ((g_partDiag[4 * 192 + t] + g_partDiag[5 * 192 + t]) +
                   (g_partDiag[6 * 192 + t] + g_partDiag[7 * 192 + t]));
        s_inv[t] = 1.0f / fmaxf(sqrtf(d), 1e-8f);
    }
    __syncthreads();

    // --- combine + normalize neg slice (t < 576); keep nv for slice sum
    float nv = 0.f;
    if (t < NEG_PER) {
        int gj = ns * NEG_PER + t;
        float raw = ((g_partNeg[0 * Q_CNT + gj] + g_partNeg[1 * Q_CNT + gj]) +
                     (g_partNeg[2 * Q_CNT + gj] + g_partNeg[3 * Q_CNT + gj])) +
                    ((g_partNeg[4 * Q_CNT + gj] + g_partNeg[5 * Q_CNT + gj]) +
                     (g_partNeg[6 * Q_CNT + gj] + g_partNeg[7 * Q_CNT + gj]));
        int r = gj / 96, c = gj % 96;
        nv = raw * s_inv[NR + r] * s_inv[c];
        s_neg[t] = (nv + THR) * 0.5f;       // hinge uses FFMA x2 (exact)
    }

    // --- combine + normalize this thread's pos value (table-driven)
    int pid = pg * HTHR + t;                // max 9215
    bool act = (pid < P_CNT);
    float posv = 0.f;
    if (act) {
        float raw = ((g_partPos[0 * P_CNT + pid] + g_partPos[1 * P_CNT + pid]) +
                     (g_partPos[2 * P_CNT + pid] + g_partPos[3 * P_CNT + pid])) +
                    ((g_partPos[4 * P_CNT + pid] + g_partPos[5 * P_CNT + pid]) +
                     (g_partPos[6 * P_CNT + pid] + g_partPos[7 * P_CNT + pid]));
        int idx  = g_pairIdx[pid];
        int invo = (pid < TRIU) ? 0 : NR;
        int i = (idx >> 8) & 0xff;
        int j = idx & 0xff;
        posv = raw * s_inv[invo + i] * s_inv[invo + j];
    }
    __syncthreads();

    // --- designated blocks record separable sums
    if (ns == 0) {
        float r = blockReduce(act ? posv : 0.f, sbuf);
        if (t == 0) g_sumP[pg] = r;
    }
    if (pg == 0) {
        float r = blockReduce(nv, sbuf);
        if (t == 0) g_sumN[ns] = r;
    }

    // --- main hinge: x = FFMA(v, 2.0, c) [imm, rt=1]; acc += |x| [FADD rt=2]
    float c = -posv;
    float s0 = 0.f, s1 = 0.f, s2 = 0.f, s3 = 0.f;
    const float4* sn4 = reinterpret_cast<const float4*>(s_neg);  // 144 vecs
    #pragma unroll 6
    for (int i = 0; i < NEG_PER / 4; i++) {
        float4 v = sn4[i];
        s0 += fabsf(__fmaf_rn(v.x, 2.0f, c));
        s1 += fabsf(__fmaf_rn(v.y, 2.0f, c));
        s2 += fabsf(__fmaf_rn(v.z, 2.0f, c));
        s3 += fabsf(__fmaf_rn(v.w, 2.0f, c));
    }
    float accf = act ? ((s0 + s1) + (s2 + s3)) : 0.f;

    float bsum = blockReduce(accf, sbuf);
    if (t == 0) g_blockSum[bid] = bsum;

    // --- last-block-done deterministic final combine (proven HB=144)
    if (t == 0) {
        __threadfence();
        unsigned old = atomicInc(&g_count, HB - 1);
        s_last = (old == HB - 1);
    }
    __syncthreads();
    if (!s_last) return;
    __threadfence();

    float vA = (t < HB)     ? g_blockSum[t] : 0.f;
    float S_abs = blockReduce(vA, sbuf);
    float vP = (t < POS_GR) ? g_sumP[t]     : 0.f;
    float S_pos = blockReduce(vP, sbuf);
    float vN = (t < NEG_SL) ? g_sumN[t]     : 0.f;
    float S_neg = blockReduce(vN, sbuf);

    if (t == 0) {
        const double P = (double)P_CNT, Q = (double)Q_CNT, thr = (double)THR;
        double Sx = P * (double)S_neg - Q * (double)S_pos + P * Q * thr;
        out[0] = (float)(0.5 * (Sx + (double)S_abs) / (P * Q));
    }
}

// ---------------- launch ----------------
extern "C" void kernel_launch(void* const* d_in, const int* in_sizes, int n_in,
                              void* d_out, int out_size) {
    const float* stereos  = (const float*)d_in[0];
    const float* astereos = (const float*)d_in[1];
    k_gram<<<21 * SPLITK, 256>>>(stereos, astereos);
    k_hinge<<<HB, HTHR>>>((float*)d_out);
}

// round 14
// speedup vs baseline: 1.0125x; 1.0125x over previous
#include <cuda_runtime.h>

#define NR      96
#define DIM     768
#define TRIU    4560
#define P_CNT   9120
#define Q_CNT   9216
#define THR     0.3f
#define SPLITK  8              // 768/8 = 96 per split
#define KS      96
#define CB      72             // combine blocks (x256 thr)
#define NEG_SL  16
#define NEG_PER 576
#define POS_GR  18
#define HTHR    512
#define HB      (NEG_SL * POS_GR)   // 288

// ---------------- device scratch ----------------
__device__ float g_partPos[SPLITK * P_CNT];
__device__ float g_partNeg[SPLITK * Q_CNT];
__device__ float g_partDiag[SPLITK * 2 * NR];
__device__ float g_pos[P_CNT];
__device__ float g_neg[Q_CNT];          // holds (n + THR) * 0.5
__device__ float g_sumP[CB];
__device__ float g_sumN[CB];
__device__ float g_blockSum[HB];

__device__ __forceinline__ int triu_base(int i) { return i * (191 - i) / 2; }
__device__ __forceinline__ int triu_idx(int i, int j) {
    return triu_base(i) + (j - i - 1);
}

// block reduce; sbuf has 32 slots; blockDim multiple of 32, <= 1024
__device__ __forceinline__ float blockReduce(float v, float* sbuf) {
    __syncthreads();
    int t = threadIdx.x;
    int nw = blockDim.x >> 5;
    #pragma unroll
    for (int o = 16; o; o >>= 1) v += __shfl_down_sync(0xffffffffu, v, o);
    if ((t & 31) == 0) sbuf[t >> 5] = v;
    __syncthreads();
    float r = 0.f;
    if (t < 32) {
        r = (t < nw) ? sbuf[t] : 0.f;
        #pragma unroll
        for (int o = 16; o; o >>= 1) r += __shfl_down_sync(0xffffffffu, r, o);
    }
    return r;   // valid at t == 0
}

// ---------------- K1: RAW grams + diag partials (168 blocks x 256) --------
__global__ void __launch_bounds__(256) k_gram(const float* __restrict__ S,
                                              const float* __restrict__ A) {
    __shared__ float As[KS][34];
    __shared__ float Bs[KS][34];

    int bx = blockIdx.x;
    int sk = bx / 21;
    int tl = bx % 21;

    int m, tr, tc;
    if (tl < 9) { m = 0; tr = tl / 3; tc = tl % 3; }
    else {
        int q = tl - 9;
        m = 1 + q / 6;
        const int TR6[6] = {0,0,0,1,1,2};
        const int TC6[6] = {0,1,2,1,2,2};
        tr = TR6[q % 6]; tc = TC6[q % 6];
    }
    // m0: neg = A x S^T; m1: S x S^T; m2: A x A^T
    const float* Ap = (m == 1) ? S : A;
    const float* Bp = (m == 2) ? A : S;

    int t  = threadIdx.x;
    int tx = t & 15, ty = t >> 4;
    int kb = sk * KS;

    // ---- prefetch whole 32x96 panels (3 float4 per thread per matrix) ----
    float4 ra[3], rb[3];
    #pragma unroll
    for (int p = 0; p < 3; p++) {
        int idx = t + p * 256;          // 0..767
        int row = idx / 24;             // 0..31
        int f4  = idx % 24;             // 0..23
        ra[p] = *(const float4*)&Ap[(tr * 32 + row) * DIM + kb + f4 * 4];
        rb[p] = *(const float4*)&Bp[(tc * 32 + row) * DIM + kb + f4 * 4];
    }
    #pragma unroll
    for (int p = 0; p < 3; p++) {
        int idx = t + p * 256;
        int row = idx / 24;
        int kk  = (idx % 24) * 4;
        As[kk + 0][row] = ra[p].x; As[kk + 1][row] = ra[p].y;
        As[kk + 2][row] = ra[p].z; As[kk + 3][row] = ra[p].w;
        Bs[kk + 0][row] = rb[p].x; Bs[kk + 1][row] = rb[p].y;
        Bs[kk + 2][row] = rb[p].z; Bs[kk + 3][row] = rb[p].w;
    }
    __syncthreads();

    float acc00 = 0.f, acc01 = 0.f, acc10 = 0.f, acc11 = 0.f;
    #pragma unroll 8
    for (int kk = 0; kk < KS; kk++) {
        float2 a = *(const float2*)&As[kk][2 * ty];
        float2 b = *(const float2*)&Bs[kk][2 * tx];
        acc00 += a.x * b.x; acc01 += a.x * b.y;
        acc10 += a.y * b.x; acc11 += a.y * b.y;
    }

    int r0 = tr * 32 + 2 * ty;
    int c0 = tc * 32 + 2 * tx;
    if (m == 0) {
        float* dst = g_partNeg + sk * Q_CNT;
        dst[r0 * 96 + c0]           = acc00;
        dst[r0 * 96 + c0 + 1]       = acc01;
        dst[(r0 + 1) * 96 + c0]     = acc10;
        dst[(r0 + 1) * 96 + c0 + 1] = acc11;
    } else {
        float* dst = g_partPos + sk * P_CNT + ((m == 2) ? TRIU : 0);
        if (r0     < c0    ) dst[triu_idx(r0,     c0    )] = acc00;
        if (r0     < c0 + 1) dst[triu_idx(r0,     c0 + 1)] = acc01;
        if (r0 + 1 < c0    ) dst[triu_idx(r0 + 1, c0    )] = acc10;
        if (r0 + 1 < c0 + 1) dst[triu_idx(r0 + 1, c0 + 1)] = acc11;
        if (r0 == c0) {  // diagonal entries -> squared row norms
            int off = (m == 1) ? 0 : NR;
            g_partDiag[sk * 2 * NR + off + r0]     = acc00;
            g_partDiag[sk * 2 * NR + off + r0 + 1] = acc11;
        }
    }
}

// ---------------- K2: combine + normalize (72 blocks x 256) ---------------
__global__ void __launch_bounds__(256) k_combine() {
    __shared__ float s_inv[2 * NR];
    __shared__ float sbuf[32];

    int t   = threadIdx.x;
    int bid = blockIdx.x;

    if (t < 2 * NR) {
        float d = ((g_partDiag[0 * 192 + t] + g_partDiag[1 * 192 + t]) +
                   (g_partDiag[2 * 192 + t] + g_partDiag[3 * 192 + t])) +
                  ((g_partDiag[4 * 192 + t] + g_partDiag[5 * 192 + t]) +
                   (g_partDiag[6 * 192 + t] + g_partDiag[7 * 192 + t]));
        s_inv[t] = 1.0f / fmaxf(sqrtf(d), 1e-8f);
    }
    __syncthreads();

    int e = bid * 256 + t;
    float pv = 0.f, nv = 0.f;
    if (e < P_CNT) {
        float raw = ((g_partPos[0 * P_CNT + e] + g_partPos[1 * P_CNT + e]) +
                     (g_partPos[2 * P_CNT + e] + g_partPos[3 * P_CNT + e])) +
                    ((g_partPos[4 * P_CNT + e] + g_partPos[5 * P_CNT + e]) +
                     (g_partPos[6 * P_CNT + e] + g_partPos[7 * P_CNT + e]));
        int invo = (e < TRIU) ? 0 : NR;
        int p    = (e < TRIU) ? e : (e - TRIU);
        // 36481 - 8p exact in fp32 (< 2^24); sqrtf off-by-one fixed below
        int i = (int)((191.0f - sqrtf((float)(36481 - 8 * p))) * 0.5f);
        while (triu_base(i + 1) <= p) ++i;
        while (triu_base(i) > p)      --i;
        int j = p - triu_base(i) + i + 1;
        pv = raw * s_inv[invo + i] * s_inv[invo + j];
        g_pos[e] = pv;
    } else if (e < P_CNT + Q_CNT) {
        int gj = e - P_CNT;
        float raw = ((g_partNeg[0 * Q_CNT + gj] + g_partNeg[1 * Q_CNT + gj]) +
                     (g_partNeg[2 * Q_CNT + gj] + g_partNeg[3 * Q_CNT + gj])) +
                    ((g_partNeg[4 * Q_CNT + gj] + g_partNeg[5 * Q_CNT + gj]) +
                     (g_partNeg[6 * Q_CNT + gj] + g_partNeg[7 * Q_CNT + gj]));
        int r = gj / 96, c = gj % 96;
        nv = raw * s_inv[NR + r] * s_inv[c];
        g_neg[gj] = (nv + THR) * 0.5f;   // halved: hinge uses FFMA x2 (exact)
    }
    float rp = blockReduce(pv, sbuf);
    if (t == 0) g_sumP[bid] = rp;
    float rn = blockReduce(nv, sbuf);
    if (t == 0) g_sumN[bid] = rn;
}

// ---------------- K3: hinge (288 blocks x 512), trivial preamble -----------
__global__ void __launch_bounds__(HTHR) k_hinge() {
    __shared__ __align__(16) float s_neg[NEG_PER];
    __shared__ float sbuf[32];

    int bid = blockIdx.x;
    int ns  = bid / POS_GR;       // 0..15
    int pg  = bid % POS_GR;       // 0..17
    int t   = threadIdx.x;

    // slice of halved negs ((n+THR)/2): 576 values, 512 threads
    int j0 = ns * NEG_PER;
    s_neg[t] = g_neg[j0 + t];
    if (t < NEG_PER - HTHR) s_neg[HTHR + t] = g_neg[j0 + HTHR + t];

    int pid = pg * HTHR + t;      // max 9215
    bool act = (pid < P_CNT);
    float c = act ? -g_pos[pid] : 0.f;
    __syncthreads();

    // x = FFMA(v, 2.0, c) [imm, rt=1]; acc = FFMA(|x|, 1.0, acc) [imm, rt=1]
    float s0 = 0.f, s1 = 0.f, s2 = 0.f, s3 = 0.f;
    const float4* sn4 = reinterpret_cast<const float4*>(s_neg);  // 144 vecs
    #pragma unroll 6
    for (int i = 0; i < NEG_PER / 4; i++) {
        float4 v = sn4[i];
        s0 = __fmaf_rn(fabsf(__fmaf_rn(v.x, 2.0f, c)), 1.0f, s0);
        s1 = __fmaf_rn(fabsf(__fmaf_rn(v.y, 2.0f, c)), 1.0f, s1);
        s2 = __fmaf_rn(fabsf(__fmaf_rn(v.z, 2.0f, c)), 1.0f, s2);
        s3 = __fmaf_rn(fabsf(__fmaf_rn(v.w, 2.0f, c)), 1.0f, s3);
    }
    float accf = act ? ((s0 + s1) + (s2 + s3)) : 0.f;

    float bsum = blockReduce(accf, sbuf);
    if (t == 0) g_blockSum[bid] = bsum;
}

// ---------------- K4: deterministic final combine (1 x 256) ----------------
__global__ void __launch_bounds__(256) k_final(float* __restrict__ out) {
    int t = threadIdx.x;
    double sb = 0.0, sp = 0.0, sn = 0.0;
    for (int i = t; i < HB; i += 256) sb += (double)g_blockSum[i];
    if (t < CB) { sp = (double)g_sumP[t]; sn = (double)g_sumN[t]; }

    __shared__ double rb[256], rp[256], rn[256];
    rb[t] = sb; rp[t] = sp; rn[t] = sn;
    __syncthreads();
    for (int s = 128; s; s >>= 1) {
        if (t < s) { rb[t] += rb[t + s]; rp[t] += rp[t + s]; rn[t] += rn[t + s]; }
        __syncthreads();
    }
    if (t == 0) {
        const double P = (double)P_CNT, Q = (double)Q_CNT, thr = (double)THR;
        double Sx = P * rn[0] - Q * rp[0] + P * Q * thr;
        out[0] = (float)(0.5 * (Sx + rb[0]) / (P * Q));
    }
}

// ---------------- launch ----------------
extern "C" void kernel_launch(void* const* d_in, const int* in_sizes, int n_in,
                              void* d_out, int out_size) {
    const float* stereos  = (const float*)d_in[0];
    const float* astereos = (const float*)d_in[1];
    k_gram<<<21 * SPLITK, 256>>>(stereos, astereos);
    k_combine<<<CB, 256>>>();
    k_hinge<<<HB, HTHR>>>();
    k_final<<<1, 256>>>((float*)d_out);
}